// round 11
// baseline (speedup 1.0000x reference)
#include <cuda_runtime.h>
#include <cuda_fp16.h>

#define NPTS 8192
#define DIM  128
#define TILE 128
#define NT   (NPTS/TILE)          // 64
#define NTILES (NT*(NT+1)/2)      // 2080
#define MARGIN 1.0f
#define EPSV 1e-16f
#define PAIR_CAP 2500000

// ---------------- device scratch ----------------
__device__ float g_S[NPTS];
__device__ float g_sq[NPTS];
__device__ int   g_lab[NPTS];
__device__ double g_loss;
__device__ unsigned long long g_cnt;
__device__ unsigned g_np;
__device__ unsigned g_done;
__device__ unsigned g_tick;
__device__ uint4 g_h[NPTS*DIM/8];    // fp16 features, 8 per uint4
__device__ uint2 g_pairs[PAIR_CAP];

// ---------------- smem layout (bytes) ----------------
#define SM_AH   0
#define SM_B(b) (32768 + (b)*32768)
#define SM_MISC 98304
#define SM_SQI  (SM_MISC)                    // 512
#define SM_LI   (SM_MISC + 512)              // 512
#define SM_SQJ(p) (SM_MISC + 1024 + (p)*512) // 2x512
#define SM_LJ(p)  (SM_MISC + 2048 + (p)*512) // 2x512
#define SM_CNT  (SM_MISC + 3072)
#define SM_TK   (SM_MISC + 3076)             // next-next ticket
#define SM_PBUF (SM_MISC + 3104)
#define PBUF_CAP 1024
#define SM_TOTAL (SM_PBUF + PBUF_CAP*8)

__device__ __forceinline__ unsigned smem_u32(const void* p) {
    unsigned a;
    asm("{ .reg .u64 t; cvta.to.shared.u64 t, %1; cvt.u32.u64 %0, t; }" : "=r"(a) : "l"(p));
    return a;
}

#define LDGSTS16(dst, src) asm volatile("cp.async.cg.shared.global [%0], [%1], 16;" :: "r"(dst), "l"(src) : "memory")
#define CP_COMMIT() asm volatile("cp.async.commit_group;" ::: "memory")
#define CP_WAIT1()  asm volatile("cp.async.wait_group 1;" ::: "memory")
#define CP_WAIT0()  asm volatile("cp.async.wait_group 0;" ::: "memory")

#define LDSM4(R, a) asm volatile( \
    "ldmatrix.sync.aligned.m8n8.x4.shared.b16 {%0,%1,%2,%3}, [%4];" \
    : "=r"((R)[0]), "=r"((R)[1]), "=r"((R)[2]), "=r"((R)[3]) : "r"(a))

#define MMA(d, a, b) asm volatile( \
    "mma.sync.aligned.m16n8k16.row.col.f32.f16.f16.f32 " \
    "{%0,%1,%2,%3}, {%4,%5,%6,%7}, {%8,%9}, {%0,%1,%2,%3};" \
    : "+f"((d)[0]), "+f"((d)[1]), "+f"((d)[2]), "+f"((d)[3]) \
    : "r"((a)[0]), "r"((a)[1]), "r"((a)[2]), "r"((a)[3]), "r"((b)[0]), "r"((b)[1]))

// closed-form upper-triangle decode: tile k -> (it, jt)
__device__ __forceinline__ void decode_tile(int k, int& it, int& jt) {
    float x = (float)NT + 0.5f;
    int i = (int)(x - sqrtf(fmaxf(x * x - 2.0f * (float)k, 0.0f)));
    int base = i * NT - (i * (i - 1)) / 2;
    if (k < base) { i--; base = i * NT - (i * (i - 1)) / 2; }
    else if (k >= base + NT - i) { i++; base = i * NT - (i * (i - 1)) / 2; }
    it = i; jt = i + (k - base);
}

// ---------------- fused prep: fp16 convert + sq + labels + init ----------------
__global__ void __launch_bounds__(256) k_prep(const float* __restrict__ f,
                                              const int* __restrict__ lab32) {
    const int b = blockIdx.x, t = threadIdx.x;
    const int idx = b * 256 + t;                 // 0..131071 (8-float granule)
    const float4* f4 = (const float4*)f;
    float4 a = f4[idx * 2], c = f4[idx * 2 + 1];
    __half2 h0 = __floats2half2_rn(a.x, a.y);
    __half2 h1 = __floats2half2_rn(a.z, a.w);
    __half2 h2 = __floats2half2_rn(c.x, c.y);
    __half2 h3 = __floats2half2_rn(c.z, c.w);
    g_h[idx] = make_uint4(*(unsigned*)&h0, *(unsigned*)&h1, *(unsigned*)&h2, *(unsigned*)&h3);
    float s = 0.0f;
    s = fmaf(a.x, a.x, s); s = fmaf(a.y, a.y, s);
    s = fmaf(a.z, a.z, s); s = fmaf(a.w, a.w, s);
    s = fmaf(c.x, c.x, s); s = fmaf(c.y, c.y, s);
    s = fmaf(c.z, c.z, s); s = fmaf(c.w, c.w, s);
    s += __shfl_xor_sync(0xffffffffu, s, 1);
    s += __shfl_xor_sync(0xffffffffu, s, 2);
    s += __shfl_xor_sync(0xffffffffu, s, 4);
    s += __shfl_xor_sync(0xffffffffu, s, 8);
    if ((t & 15) == 0) g_sq[idx >> 4] = s;
    if (b < 32) {
        const int i2 = b * 256 + t;
        int odd = lab32[2 * t + 1];
        int nz = __syncthreads_or(odd != 0);     // nz -> int32 labels
        g_lab[i2] = lab32[i2 * (nz ? 1 : 2)];
        g_S[i2] = 0.0f;
        if (i2 == 0) { g_loss = 0.0; g_cnt = 0ull; g_np = 0u; g_done = 0u; g_tick = 0u; }
    }
}

// ---------------- stage helpers ----------------
// 256B rows, 16B granules, swizzle: granule q at row r -> q ^ (r&7)
__device__ __forceinline__ void issue_B(unsigned sb, int buf, int jt, int t) {
    const char* sh = (const char*)(g_h + (size_t)jt * 2048);
    const unsigned db = sb + SM_B(buf);
    #pragma unroll
    for (int i = 0; i < 8; i++) {
        int g = i * 256 + t;
        int r = g >> 4, q = g & 15;
        unsigned dsw = (unsigned)(r * 256 + ((q ^ (r & 7)) << 4));
        LDGSTS16(db + dsw, sh + (size_t)g * 16);
    }
}
__device__ __forceinline__ void load_A(char* smem, int it, int t) {
    const uint4* sh = g_h + (size_t)it * 2048;
    #pragma unroll
    for (int i = 0; i < 8; i++) {
        int g = i * 256 + t;
        int r = g >> 4, q = g & 15;
        unsigned dsw = (unsigned)(r * 256 + ((q ^ (r & 7)) << 4));
        *(uint4*)(smem + SM_AH + dsw) = sh[g];
    }
}

// warp-0-only pair flush: pbuf -> g_pairs
__device__ __forceinline__ void flush_pairs_w0(unsigned* s_cnt, uint2* pbuf, int lane) {
    unsigned cnt = *s_cnt;
    if (cnt > PBUF_CAP) cnt = PBUF_CAP;
    unsigned gb = 0;
    if (lane == 0 && cnt) gb = atomicAdd(&g_np, cnt);
    gb = __shfl_sync(0xffffffffu, gb, 0);
    for (unsigned i = lane; i < cnt; i += 32) g_pairs[gb + i] = pbuf[i];
    if (lane == 0) *s_cnt = 0u;
}

// ---------------- persistent HMMA Gram + fused epilogue (ticket-scheduled) ----------------
__global__ void __launch_bounds__(256, 2) k_S() {
    extern __shared__ char smem[];
    const unsigned sb = smem_u32(smem);
    float* s_sqi  = (float*)(smem + SM_SQI);
    int*   s_li   = (int*)  (smem + SM_LI);
    unsigned* s_cnt = (unsigned*)(smem + SM_CNT);
    int*   s_tk   = (int*)(smem + SM_TK);
    uint2* pbuf = (uint2*)(smem + SM_PBUF);

    const int t = threadIdx.x, w = t >> 5, lane = t & 31;

    // grab first two tickets
    if (t == 0) {
        s_tk[0] = (int)atomicAdd(&g_tick, 1u);
        s_tk[1] = (int)atomicAdd(&g_tick, 1u);
        *s_cnt = 0u;
    }
    __syncthreads();
    int kc = s_tk[0], kn = s_tk[1];
    if (kc >= NTILES) return;

    {   // prefetch pipeline (depth 2)
        int it0, jt0; decode_tile(kc, it0, jt0);
        issue_B(sb, 0, jt0, t); CP_COMMIT();
        if (kn < NTILES) {
            int it1, jt1; decode_tile(kn, it1, jt1);
            issue_B(sb, 1, jt1, t); CP_COMMIT();
        }
    }

    // warp subtile: 32 rows x 64 cols
    const int mb = (w & 3) * 32;
    const int nb = (w >> 2) * 64;
    const int a_row = mb + (lane & 15);
    const int a_ch  = lane >> 4;
    const int b_row = nb + (lane & 7) + ((lane >> 4) << 3);
    const int b_ch  = (lane >> 3) & 1;

    int curA = -1;
    int iter = 0;
    bool havePrev = false;

    while (kc < NTILES) {
        const int buf = iter & 1;
        int cit, cjt; decode_tile(kc, cit, cjt);
        const bool offdiag = (cit != cjt);
        const bool have_nxt = (kn < NTILES);
        if (have_nxt) CP_WAIT1(); else CP_WAIT0();

        if (cit != curA) {
            load_A(smem, cit, t);
            if (t < 128) {
                s_sqi[t] = g_sq[cit * TILE + t];
                s_li[t]  = g_lab[cit * TILE + t];
            }
            curA = cit;
        }
        float* s_sqj = (float*)(smem + SM_SQJ(buf));
        int*   s_lj  = (int*)  (smem + SM_LJ(buf));
        if (t < 128) {
            s_sqj[t] = g_sq[cjt * TILE + t];
            s_lj[t]  = g_lab[cjt * TILE + t];
        }
        // ticket for iter+2
        if (t == 0)
            s_tk[buf] = have_nxt ? (int)atomicAdd(&g_tick, 1u) : NTILES;
        __syncthreads();   // SYNC1: B/A/staging visible; prev epilogue complete
        const int knn = s_tk[buf];

        // warp 0: flush previous tile's pairs while others start MMA
        if (w == 0 && havePrev) flush_pairs_w0(s_cnt, pbuf, lane);
        havePrev = true;

        // ---- MMA ----
        float acc[2][8][4];
        #pragma unroll
        for (int mt = 0; mt < 2; mt++)
            #pragma unroll
            for (int nt = 0; nt < 8; nt++)
                #pragma unroll
                for (int e = 0; e < 4; e++) acc[mt][nt][e] = 0.0f;

        const unsigned bbase = sb + SM_B(buf);
        #pragma unroll
        for (int ks = 0; ks < 8; ks++) {
            unsigned ah[2][4], bh[8][2];
            #pragma unroll
            for (int mt = 0; mt < 2; mt++) {
                int r = a_row + mt * 16;
                unsigned addr = sb + SM_AH + r * 256 + (((ks * 2 + a_ch) ^ (r & 7)) << 4);
                LDSM4(ah[mt], addr);
            }
            #pragma unroll
            for (int np = 0; np < 4; np++) {
                int r = b_row + np * 16;
                unsigned addr = bbase + r * 256 + (((ks * 2 + b_ch) ^ (r & 7)) << 4);
                unsigned th[4];
                LDSM4(th, addr);
                bh[2*np][0] = th[0]; bh[2*np][1] = th[1];
                bh[2*np+1][0] = th[2]; bh[2*np+1][1] = th[3];
            }
            #pragma unroll
            for (int mt = 0; mt < 2; mt++)
                #pragma unroll
                for (int nt = 0; nt < 8; nt++)
                    MMA(acc[mt][nt], ah[mt], bh[nt]);
        }
        __syncthreads();   // SYNC2: B(buf) consumed; flush done before new pbuf writes

        // prefetch B for ticket knn into freed buffer; overlaps epilogue
        if (knn < NTILES) {
            int itn, jtn; decode_tile(knn, itn, jtn);
            issue_B(sb, buf, jtn, t); CP_COMMIT();
        }

        // ---- epilogue ----
        const int r4 = lane >> 2, cb = (lane & 3) * 2;
        float sqi_r[4]; int li_r[4];
        #pragma unroll
        for (int mt = 0; mt < 2; mt++)
            #pragma unroll
            for (int h = 0; h < 2; h++) {
                int iL = mb + mt * 16 + r4 + h * 8;
                sqi_r[mt*2+h] = s_sqi[iL]; li_r[mt*2+h] = s_li[iL];
            }

        float rp[4] = {0.f, 0.f, 0.f, 0.f};
        float cp[16];
        #pragma unroll
        for (int q = 0; q < 16; q++) cp[q] = 0.0f;

        #pragma unroll
        for (int mt = 0; mt < 2; mt++)
            #pragma unroll
            for (int nt = 0; nt < 8; nt++)
                #pragma unroll
                for (int e = 0; e < 4; e++) {
                    const int h = e >> 1, o = e & 1;
                    const int jL = nb + nt * 8 + cb + o;
                    float d2 = fmaxf(sqi_r[mt*2+h] + s_sqj[jL] - 2.0f * acc[mt][nt][e], EPSV);
                    float d;
                    asm("sqrt.approx.f32 %0, %1;" : "=f"(d) : "f"(d2));
                    if (li_r[mt*2+h] != s_lj[jL]) {
                        float ex = __expf(MARGIN - d);
                        rp[mt*2+h] += ex;
                        cp[nt*2+o] += ex;
                    } else {
                        unsigned kk = atomicAdd(s_cnt, 1u);
                        unsigned gi = cit * TILE + mb + mt * 16 + r4 + h * 8;
                        unsigned gj = cjt * TILE + jL;
                        unsigned packed = gi | (gj << 13) | (offdiag ? (1u << 26) : 0u);
                        uint2 rec = make_uint2(packed, __float_as_uint(d));
                        if (kk < PBUF_CAP) pbuf[kk] = rec;
                        else { unsigned gg = atomicAdd(&g_np, 1u); if (gg < PAIR_CAP) g_pairs[gg] = rec; }
                    }
                }

        // row sums -> direct global RED
        #pragma unroll
        for (int q = 0; q < 4; q++) {
            float v = rp[q];
            v += __shfl_xor_sync(0xffffffffu, v, 1);
            v += __shfl_xor_sync(0xffffffffu, v, 2);
            if ((lane & 3) == 0)
                atomicAdd(&g_S[cit * TILE + mb + (q >> 1) * 16 + r4 + (q & 1) * 8], v);
        }
        // col sums -> direct global RED
        if (offdiag) {
            #pragma unroll
            for (int q = 0; q < 16; q++) {
                float v = cp[q];
                v += __shfl_xor_sync(0xffffffffu, v, 4);
                v += __shfl_xor_sync(0xffffffffu, v, 8);
                v += __shfl_xor_sync(0xffffffffu, v, 16);
                if ((lane >> 2) == 0)
                    atomicAdd(&g_S[cjt * TILE + nb + (q >> 1) * 8 + cb + (q & 1)], v);
            }
        }

        kc = kn; kn = knn; iter++;
    }

    __syncthreads();       // last tile's epilogue complete
    if (w == 0) flush_pairs_w0(s_cnt, pbuf, lane);
}

// ---------------- positive-pair loss + fused finalize ----------------
__global__ void __launch_bounds__(256) k_pairs(float* out) {
    __shared__ float rf[256];
    __shared__ int   ri[256];
    unsigned n = g_np; if (n > PAIR_CAP) n = PAIR_CAP;
    float part = 0.0f; int c = 0;
    for (unsigned idx = blockIdx.x * 256u + threadIdx.x; idx < n; idx += gridDim.x * 256u) {
        uint2 p = g_pairs[idx];
        int i = p.x & 0x1FFF, j = (p.x >> 13) & 0x1FFF;
        int wt = (p.x & (1u << 26)) ? 2 : 1;
        float d = __uint_as_float(p.y);
        float J = __logf(g_S[i] + g_S[j]) + d;
        float h = fmaxf(J, 0.0f);
        part += (float)wt * h * h; c += wt;
    }
    int t = threadIdx.x;
    rf[t] = part; ri[t] = c;
    __syncthreads();
    for (int off = 128; off; off >>= 1) {
        if (t < off) { rf[t] += rf[t + off]; ri[t] += ri[t + off]; }
        __syncthreads();
    }
    if (t == 0) {
        atomicAdd(&g_loss, (double)rf[0]);
        atomicAdd(&g_cnt, (unsigned long long)ri[0]);
        __threadfence();
        unsigned v = atomicAdd(&g_done, 1u);
        if (v == gridDim.x - 1)
            out[0] = (float)(g_loss / (2.0 * (double)g_cnt));
    }
}

// ---------------- launcher ----------------
extern "C" void kernel_launch(void* const* d_in, const int* in_sizes, int n_in,
                              void* d_out, int out_size) {
    const float* f     = (const float*)d_in[0];
    const int*   lab32 = (const int*)d_in[1];
    float*       out   = (float*)d_out;

    int dev = 0, nsm = 0;
    if (cudaGetDevice(&dev) != cudaSuccess ||
        cudaDeviceGetAttribute(&nsm, cudaDevAttrMultiProcessorCount, dev) != cudaSuccess ||
        nsm <= 0)
        nsm = 148;

    cudaFuncSetAttribute(k_S, cudaFuncAttributeMaxDynamicSharedMemorySize, SM_TOTAL);

    k_prep<<<512, 256>>>(f, lab32);
    k_S<<<nsm * 2, 256, SM_TOTAL>>>();
    k_pairs<<<512, 256>>>(out);
}

// round 12
// speedup vs baseline: 1.1627x; 1.1627x over previous
#include <cuda_runtime.h>
#include <cuda_fp16.h>

#define NPTS 8192
#define DIM  128
#define TILE 128
#define NT   (NPTS/TILE)          // 64
#define NTILES (NT*(NT+1)/2)      // 2080
#define MARGIN 1.0f
#define EPSV 1e-16f
#define PAIR_CAP 2500000

// ---------------- device scratch ----------------
__device__ float g_S[NPTS];
__device__ float g_sq[NPTS];
__device__ int   g_lab[NPTS];
__device__ double g_loss;
__device__ unsigned long long g_cnt;
__device__ unsigned g_np;
__device__ unsigned g_done;
__device__ uint4 g_h[NPTS*DIM/8];    // fp16 features, 8 per uint4
__device__ uint2 g_pairs[PAIR_CAP];

// ---------------- smem layout (bytes) ----------------
#define SM_AH   0
#define SM_B(b) (32768 + (b)*32768)
#define SM_SQI  98304                        // 512
#define SM_LI   98816                        // 512
#define SM_SQJ(p) (99328 + (p)*512)          // 2x512
#define SM_LJ(p)  (100352 + (p)*512)         // 2x512
#define SM_CNT  101376                       // 2x4
#define SM_PBUF(p) (101408 + (p)*4096)       // 2x512 uint2
#define PBUF_CAP 512
#define SM_TOTAL (101408 + 8192)

__device__ __forceinline__ unsigned smem_u32(const void* p) {
    unsigned a;
    asm("{ .reg .u64 t; cvta.to.shared.u64 t, %1; cvt.u32.u64 %0, t; }" : "=r"(a) : "l"(p));
    return a;
}

#define LDGSTS16(dst, src) asm volatile("cp.async.cg.shared.global [%0], [%1], 16;" :: "r"(dst), "l"(src) : "memory")
#define CP_COMMIT() asm volatile("cp.async.commit_group;" ::: "memory")
#define CP_WAIT1()  asm volatile("cp.async.wait_group 1;" ::: "memory")
#define CP_WAIT0()  asm volatile("cp.async.wait_group 0;" ::: "memory")

#define LDSM4(R, a) asm volatile( \
    "ldmatrix.sync.aligned.m8n8.x4.shared.b16 {%0,%1,%2,%3}, [%4];" \
    : "=r"((R)[0]), "=r"((R)[1]), "=r"((R)[2]), "=r"((R)[3]) : "r"(a))

#define MMA(d, a, b) asm volatile( \
    "mma.sync.aligned.m16n8k16.row.col.f32.f16.f16.f32 " \
    "{%0,%1,%2,%3}, {%4,%5,%6,%7}, {%8,%9}, {%0,%1,%2,%3};" \
    : "+f"((d)[0]), "+f"((d)[1]), "+f"((d)[2]), "+f"((d)[3]) \
    : "r"((a)[0]), "r"((a)[1]), "r"((a)[2]), "r"((a)[3]), "r"((b)[0]), "r"((b)[1]))

// ---------------- fused prep: fp16 convert + sq + labels + init ----------------
__global__ void __launch_bounds__(256) k_prep(const float* __restrict__ f,
                                              const int* __restrict__ lab32) {
    const int b = blockIdx.x, t = threadIdx.x;
    const int idx = b * 256 + t;                 // 0..131071 (8-float granule)
    const float4* f4 = (const float4*)f;
    float4 a = f4[idx * 2], c = f4[idx * 2 + 1];
    __half2 h0 = __floats2half2_rn(a.x, a.y);
    __half2 h1 = __floats2half2_rn(a.z, a.w);
    __half2 h2 = __floats2half2_rn(c.x, c.y);
    __half2 h3 = __floats2half2_rn(c.z, c.w);
    g_h[idx] = make_uint4(*(unsigned*)&h0, *(unsigned*)&h1, *(unsigned*)&h2, *(unsigned*)&h3);
    float s = 0.0f;
    s = fmaf(a.x, a.x, s); s = fmaf(a.y, a.y, s);
    s = fmaf(a.z, a.z, s); s = fmaf(a.w, a.w, s);
    s = fmaf(c.x, c.x, s); s = fmaf(c.y, c.y, s);
    s = fmaf(c.z, c.z, s); s = fmaf(c.w, c.w, s);
    s += __shfl_xor_sync(0xffffffffu, s, 1);
    s += __shfl_xor_sync(0xffffffffu, s, 2);
    s += __shfl_xor_sync(0xffffffffu, s, 4);
    s += __shfl_xor_sync(0xffffffffu, s, 8);
    if ((t & 15) == 0) g_sq[idx >> 4] = s;
    if (b < 32) {
        const int i2 = b * 256 + t;
        int odd = lab32[2 * t + 1];
        int nz = __syncthreads_or(odd != 0);     // nz -> int32 labels
        g_lab[i2] = lab32[i2 * (nz ? 1 : 2)];
        g_S[i2] = 0.0f;
        if (i2 == 0) { g_loss = 0.0; g_cnt = 0ull; g_np = 0u; g_done = 0u; }
    }
}

// ---------------- stage helpers ----------------
// 256B rows, 16B granules, swizzle: granule q at row r -> q ^ (r&7)
__device__ __forceinline__ void issue_B(unsigned sb, int buf, int jt, int t) {
    const char* sh = (const char*)(g_h + (size_t)jt * 2048);
    const unsigned db = sb + SM_B(buf);
    #pragma unroll
    for (int i = 0; i < 8; i++) {
        int g = i * 256 + t;
        int r = g >> 4, q = g & 15;
        unsigned dsw = (unsigned)(r * 256 + ((q ^ (r & 7)) << 4));
        LDGSTS16(db + dsw, sh + (size_t)g * 16);
    }
}
__device__ __forceinline__ void load_A(char* smem, int it, int t) {
    const uint4* sh = g_h + (size_t)it * 2048;
    #pragma unroll
    for (int i = 0; i < 8; i++) {
        int g = i * 256 + t;
        int r = g >> 4, q = g & 15;
        unsigned dsw = (unsigned)(r * 256 + ((q ^ (r & 7)) << 4));
        *(uint4*)(smem + SM_AH + dsw) = sh[g];
    }
}

// warp-0-only pair flush
__device__ __forceinline__ void flush_pairs_w0(unsigned* s_cnt, uint2* pbuf, int lane) {
    unsigned cnt = *s_cnt;
    if (cnt > PBUF_CAP) cnt = PBUF_CAP;
    unsigned gb = 0;
    if (lane == 0 && cnt) gb = atomicAdd(&g_np, cnt);
    gb = __shfl_sync(0xffffffffu, gb, 0);
    for (unsigned i = lane; i < cnt; i += 32) g_pairs[gb + i] = pbuf[i];
    if (lane == 0) *s_cnt = 0u;
}

__device__ __forceinline__ void advance(int& it, int& jt) {
    jt++; if (jt == NT) { it++; jt = it; }
}

// ---------------- persistent HMMA Gram + fused epilogue (1 barrier/tile) ----------------
__global__ void __launch_bounds__(256, 2) k_S() {
    extern __shared__ char smem[];
    const unsigned sb = smem_u32(smem);
    float* s_sqi  = (float*)(smem + SM_SQI);
    int*   s_li   = (int*)  (smem + SM_LI);
    unsigned* s_cnt = (unsigned*)(smem + SM_CNT);

    const int t = threadIdx.x, w = t >> 5, lane = t & 31;

    // balanced contiguous static split
    const int nb_ = gridDim.x;
    const int basec = NTILES / nb_, rem = NTILES % nb_;
    const int start = blockIdx.x * basec + min(blockIdx.x, rem);
    const int end = start + basec + (blockIdx.x < rem ? 1 : 0);
    if (start >= end) return;

    int cit = 0, base = 0;
    while (start >= base + (NT - cit)) { base += NT - cit; cit++; }
    int cjt = cit + (start - base);
    int nit = cit, njt = cjt; advance(nit, njt);     // tile k+1
    int pit = nit, pjt = njt; advance(pit, pjt);     // tile k+2

    // ---- preloop staging ----
    load_A(smem, cit, t);
    if (t < 128) {
        s_sqi[t] = g_sq[cit * TILE + t];
        s_li[t]  = g_lab[cit * TILE + t];
        *(float*)(smem + SM_SQJ(start & 1) + t * 4) = g_sq[cjt * TILE + t];
        *(int*)  (smem + SM_LJ(start & 1)  + t * 4) = g_lab[cjt * TILE + t];
    }
    issue_B(sb, start & 1, cjt, t); CP_COMMIT();
    if (start + 1 < end) { issue_B(sb, (start + 1) & 1, njt, t); CP_COMMIT(); }
    if (t == 0) { s_cnt[0] = 0u; s_cnt[1] = 0u; }
    __syncthreads();

    // warp subtile: 32 rows x 64 cols
    const int mb = (w & 3) * 32;
    const int nb = (w >> 2) * 64;
    const int a_row = mb + (lane & 15);
    const int a_ch  = lane >> 4;
    const int b_row = nb + (lane & 7) + ((lane >> 4) << 3);
    const int b_ch  = (lane >> 3) & 1;

    for (int k = start; k < end; k++) {
        const int buf = k & 1;
        const bool offdiag = (cit != cjt);
        float* s_sqj = (float*)(smem + SM_SQJ(buf));
        int*   s_lj  = (int*)  (smem + SM_LJ(buf));
        uint2* pbuf  = (uint2*)(smem + SM_PBUF(buf));

        if (k + 1 < end) CP_WAIT1(); else CP_WAIT0();

        // ---- MMA ----
        float acc[2][8][4];
        #pragma unroll
        for (int mt = 0; mt < 2; mt++)
            #pragma unroll
            for (int nt = 0; nt < 8; nt++)
                #pragma unroll
                for (int e = 0; e < 4; e++) acc[mt][nt][e] = 0.0f;

        const unsigned bbase = sb + SM_B(buf);
        #pragma unroll
        for (int ks = 0; ks < 8; ks++) {
            unsigned ah[2][4], bh[8][2];
            #pragma unroll
            for (int mt = 0; mt < 2; mt++) {
                int r = a_row + mt * 16;
                unsigned addr = sb + SM_AH + r * 256 + (((ks * 2 + a_ch) ^ (r & 7)) << 4);
                LDSM4(ah[mt], addr);
            }
            #pragma unroll
            for (int np = 0; np < 4; np++) {
                int r = b_row + np * 16;
                unsigned addr = bbase + r * 256 + (((ks * 2 + b_ch) ^ (r & 7)) << 4);
                unsigned th[4];
                LDSM4(th, addr);
                bh[2*np][0] = th[0]; bh[2*np][1] = th[1];
                bh[2*np+1][0] = th[2]; bh[2*np+1][1] = th[3];
            }
            #pragma unroll
            for (int mt = 0; mt < 2; mt++)
                #pragma unroll
                for (int nt = 0; nt < 8; nt++)
                    MMA(acc[mt][nt], ah[mt], bh[nt]);
        }

        // stage sqj/lab for tile k+1 into opposite parity (last read finished
        // before the previous end-of-tile barrier)
        if (k + 1 < end && t < 128) {
            *(float*)(smem + SM_SQJ(1 - buf) + t * 4) = g_sq[njt * TILE + t];
            *(int*)  (smem + SM_LJ(1 - buf)  + t * 4) = g_lab[njt * TILE + t];
        }

        // ---- epilogue (no barrier since MMA: own-warp data only) ----
        const int r4 = lane >> 2, cb = (lane & 3) * 2;
        float sqi_r[4]; int li_r[4];
        #pragma unroll
        for (int mt = 0; mt < 2; mt++)
            #pragma unroll
            for (int h = 0; h < 2; h++) {
                int iL = mb + mt * 16 + r4 + h * 8;
                sqi_r[mt*2+h] = s_sqi[iL]; li_r[mt*2+h] = s_li[iL];
            }

        float rp[4] = {0.f, 0.f, 0.f, 0.f};
        float cp[16];
        #pragma unroll
        for (int q = 0; q < 16; q++) cp[q] = 0.0f;

        #pragma unroll
        for (int mt = 0; mt < 2; mt++)
            #pragma unroll
            for (int nt = 0; nt < 8; nt++)
                #pragma unroll
                for (int e = 0; e < 4; e++) {
                    const int h = e >> 1, o = e & 1;
                    const int jL = nb + nt * 8 + cb + o;
                    float d2 = fmaxf(sqi_r[mt*2+h] + s_sqj[jL] - 2.0f * acc[mt][nt][e], EPSV);
                    float d;
                    asm("sqrt.approx.f32 %0, %1;" : "=f"(d) : "f"(d2));
                    if (li_r[mt*2+h] != s_lj[jL]) {
                        float ex = __expf(MARGIN - d);
                        rp[mt*2+h] += ex;
                        cp[nt*2+o] += ex;
                    } else {
                        unsigned kk = atomicAdd(&s_cnt[buf], 1u);
                        unsigned gi = cit * TILE + mb + mt * 16 + r4 + h * 8;
                        unsigned gj = cjt * TILE + jL;
                        unsigned packed = gi | (gj << 13) | (offdiag ? (1u << 26) : 0u);
                        uint2 rec = make_uint2(packed, __float_as_uint(d));
                        if (kk < PBUF_CAP) pbuf[kk] = rec;
                        else { unsigned gg = atomicAdd(&g_np, 1u); if (gg < PAIR_CAP) g_pairs[gg] = rec; }
                    }
                }

        // row sums -> direct global RED
        #pragma unroll
        for (int q = 0; q < 4; q++) {
            float v = rp[q];
            v += __shfl_xor_sync(0xffffffffu, v, 1);
            v += __shfl_xor_sync(0xffffffffu, v, 2);
            if ((lane & 3) == 0)
                atomicAdd(&g_S[cit * TILE + mb + (q >> 1) * 16 + r4 + (q & 1) * 8], v);
        }
        // col sums -> direct global RED
        if (offdiag) {
            #pragma unroll
            for (int q = 0; q < 16; q++) {
                float v = cp[q];
                v += __shfl_xor_sync(0xffffffffu, v, 4);
                v += __shfl_xor_sync(0xffffffffu, v, 8);
                v += __shfl_xor_sync(0xffffffffu, v, 16);
                if ((lane >> 2) == 0)
                    atomicAdd(&g_S[cjt * TILE + nb + (q >> 1) * 8 + cb + (q & 1)], v);
            }
        }

        __syncthreads();     // SINGLE end-of-tile barrier: MMA(k)+epilogue(k) done everywhere

        // B(buf) is free: prefetch tile k+2 (consumed after next barrier)
        if (k + 2 < end) { issue_B(sb, buf, pjt, t); CP_COMMIT(); }

        // warp 0 drains this tile's pair buffer while others proceed
        if (w == 0) flush_pairs_w0(&s_cnt[buf], pbuf, lane);

        // A-band change: reload + extra barrier (rare, ~1-2 per CTA)
        if (k + 1 < end && nit != cit) {
            load_A(smem, nit, t);
            if (t < 128) {
                s_sqi[t] = g_sq[nit * TILE + t];
                s_li[t]  = g_lab[nit * TILE + t];
            }
            __syncthreads();
        }

        cit = nit; cjt = njt;
        nit = pit; njt = pjt;
        advance(pit, pjt);
    }
}

// ---------------- positive-pair loss + fused finalize ----------------
__global__ void __launch_bounds__(256) k_pairs(float* out) {
    __shared__ float rf[256];
    __shared__ int   ri[256];
    unsigned n = g_np; if (n > PAIR_CAP) n = PAIR_CAP;
    float part = 0.0f; int c = 0;
    for (unsigned idx = blockIdx.x * 256u + threadIdx.x; idx < n; idx += gridDim.x * 256u) {
        uint2 p = g_pairs[idx];
        int i = p.x & 0x1FFF, j = (p.x >> 13) & 0x1FFF;
        int wt = (p.x & (1u << 26)) ? 2 : 1;
        float d = __uint_as_float(p.y);
        float J = __logf(g_S[i] + g_S[j]) + d;
        float h = fmaxf(J, 0.0f);
        part += (float)wt * h * h; c += wt;
    }
    int t = threadIdx.x;
    rf[t] = part; ri[t] = c;
    __syncthreads();
    for (int off = 128; off; off >>= 1) {
        if (t < off) { rf[t] += rf[t + off]; ri[t] += ri[t + off]; }
        __syncthreads();
    }
    if (t == 0) {
        atomicAdd(&g_loss, (double)rf[0]);
        atomicAdd(&g_cnt, (unsigned long long)ri[0]);
        __threadfence();
        unsigned v = atomicAdd(&g_done, 1u);
        if (v == gridDim.x - 1)
            out[0] = (float)(g_loss / (2.0 * (double)g_cnt));
    }
}

// ---------------- launcher ----------------
extern "C" void kernel_launch(void* const* d_in, const int* in_sizes, int n_in,
                              void* d_out, int out_size) {
    const float* f     = (const float*)d_in[0];
    const int*   lab32 = (const int*)d_in[1];
    float*       out   = (float*)d_out;

    int dev = 0, nsm = 0;
    if (cudaGetDevice(&dev) != cudaSuccess ||
        cudaDeviceGetAttribute(&nsm, cudaDevAttrMultiProcessorCount, dev) != cudaSuccess ||
        nsm <= 0)
        nsm = 148;

    cudaFuncSetAttribute(k_S, cudaFuncAttributeMaxDynamicSharedMemorySize, SM_TOTAL);

    k_prep<<<512, 256>>>(f, lab32);
    k_S<<<nsm * 2, 256, SM_TOTAL>>>();
    k_pairs<<<512, 256>>>(out);
}

// round 16
// speedup vs baseline: 1.2012x; 1.0332x over previous
#include <cuda_runtime.h>
#include <cuda_fp16.h>

#define NPTS 8192
#define DIM  128
#define TILE 128
#define NT   (NPTS/TILE)          // 64
#define NTILES (NT*(NT+1)/2)      // 2080
#define MARGIN 1.0f
#define EPSV 1e-16f
#define PAIR_CAP 2500000
#define SSCALE 2.44140625e-4f     // 2^-12

// ---------------- device scratch ----------------
__device__ float g_S[NPTS];
__device__ float g_sq[NPTS];
__device__ int   g_lab[NPTS];
__device__ double g_loss;
__device__ unsigned long long g_cnt;
__device__ unsigned g_np;
__device__ unsigned g_done;
__device__ uint4 g_h[NPTS*DIM/8];    // fp16 features, 8 per uint4
__device__ uint2 g_pairs[PAIR_CAP];

// ---------------- smem layout (bytes) ----------------
#define SM_AH   0
#define SM_B(b) (32768 + (b)*32768)
#define SM_SQI  98304                        // 512
#define SM_LI   98816                        // 512
#define SM_SQJ(p) (99328 + (p)*512)          // 2x512
#define SM_LJ(p)  (100352 + (p)*512)         // 2x512
#define SM_CNT  101376                       // 2x4
#define SM_PBUF(p) (101408 + (p)*4096)       // 2x512 uint2
#define PBUF_CAP 512
#define SM_TOTAL (101408 + 8192)

__device__ __forceinline__ unsigned smem_u32(const void* p) {
    unsigned a;
    asm("{ .reg .u64 t; cvta.to.shared.u64 t, %1; cvt.u32.u64 %0, t; }" : "=r"(a) : "l"(p));
    return a;
}

#define LDGSTS16(dst, src) asm volatile("cp.async.cg.shared.global [%0], [%1], 16;" :: "r"(dst), "l"(src) : "memory")
#define CP_COMMIT() asm volatile("cp.async.commit_group;" ::: "memory")
#define CP_WAIT1()  asm volatile("cp.async.wait_group 1;" ::: "memory")
#define CP_WAIT0()  asm volatile("cp.async.wait_group 0;" ::: "memory")

#define LDSM4(R, a) asm volatile( \
    "ldmatrix.sync.aligned.m8n8.x4.shared.b16 {%0,%1,%2,%3}, [%4];" \
    : "=r"((R)[0]), "=r"((R)[1]), "=r"((R)[2]), "=r"((R)[3]) : "r"(a))

#define MMA(d, a, b) asm volatile( \
    "mma.sync.aligned.m16n8k16.row.col.f32.f16.f16.f32 " \
    "{%0,%1,%2,%3}, {%4,%5,%6,%7}, {%8,%9}, {%0,%1,%2,%3};" \
    : "+f"((d)[0]), "+f"((d)[1]), "+f"((d)[2]), "+f"((d)[3]) \
    : "r"((a)[0]), "r"((a)[1]), "r"((a)[2]), "r"((a)[3]), "r"((b)[0]), "r"((b)[1]))

// packed helpers (Blackwell f32x2 + f16x2)
#define PACK2(out, lo, hi)  asm("mov.b64 %0, {%1, %2};" : "=l"(out) : "f"(lo), "f"(hi))
#define UNPK2(lo, hi, in)   asm("mov.b64 {%0, %1}, %2;" : "=f"(lo), "=f"(hi) : "l"(in))
#define FMAX2(d, a, b, c)   asm("fma.rn.f32x2 %0, %1, %2, %3;" : "=l"(d) : "l"(a), "l"(b), "l"(c))
#define ADDX2(d, a, b)      asm("add.rn.f32x2 %0, %1, %2;" : "=l"(d) : "l"(a), "l"(b))
#define CVTH2(d, hi, lo)    asm("cvt.rn.f16x2.f32 %0, %1, %2;" : "=r"(d) : "f"(hi), "f"(lo))
#define EX2H2(d, a)         asm("ex2.approx.f16x2 %0, %1;" : "=r"(d) : "r"(a))
#define HADD2V(d, a, b)     asm("add.rn.f16x2 %0, %1, %2;" : "=r"(d) : "r"(a), "r"(b))
#define H2TOF(lo, hi, v)    asm("{ .reg .f16 l, h; mov.b32 {l, h}, %2; cvt.f32.f16 %0, l; cvt.f32.f16 %1, h; }" : "=f"(lo), "=f"(hi) : "r"(v))

// ---------------- fused prep: fp16 convert + sq + labels + init ----------------
__global__ void __launch_bounds__(256) k_prep(const float* __restrict__ f,
                                              const int* __restrict__ lab32) {
    const int b = blockIdx.x, t = threadIdx.x;
    const int idx = b * 256 + t;                 // 0..131071 (8-float granule)
    const float4* f4 = (const float4*)f;
    float4 a = f4[idx * 2], c = f4[idx * 2 + 1];
    __half2 h0 = __floats2half2_rn(a.x, a.y);
    __half2 h1 = __floats2half2_rn(a.z, a.w);
    __half2 h2 = __floats2half2_rn(c.x, c.y);
    __half2 h3 = __floats2half2_rn(c.z, c.w);
    g_h[idx] = make_uint4(*(unsigned*)&h0, *(unsigned*)&h1, *(unsigned*)&h2, *(unsigned*)&h3);
    float s = 0.0f;
    s = fmaf(a.x, a.x, s); s = fmaf(a.y, a.y, s);
    s = fmaf(a.z, a.z, s); s = fmaf(a.w, a.w, s);
    s = fmaf(c.x, c.x, s); s = fmaf(c.y, c.y, s);
    s = fmaf(c.z, c.z, s); s = fmaf(c.w, c.w, s);
    s += __shfl_xor_sync(0xffffffffu, s, 1);
    s += __shfl_xor_sync(0xffffffffu, s, 2);
    s += __shfl_xor_sync(0xffffffffu, s, 4);
    s += __shfl_xor_sync(0xffffffffu, s, 8);
    if ((t & 15) == 0) g_sq[idx >> 4] = s;
    if (b < 32) {
        const int i2 = b * 256 + t;
        int odd = lab32[2 * t + 1];
        int nz = __syncthreads_or(odd != 0);     // nz -> int32 labels
        g_lab[i2] = lab32[i2 * (nz ? 1 : 2)];
        g_S[i2] = 0.0f;
        if (i2 == 0) { g_loss = 0.0; g_cnt = 0ull; g_np = 0u; g_done = 0u; }
    }
}

// ---------------- stage helpers ----------------
// 256B rows, 16B granules, swizzle: granule q at row r -> q ^ (r&7)
__device__ __forceinline__ void issue_B(unsigned sb, int buf, int jt, int t) {
    const char* sh = (const char*)(g_h + (size_t)jt * 2048);
    const unsigned db = sb + SM_B(buf);
    #pragma unroll
    for (int i = 0; i < 8; i++) {
        int g = i * 256 + t;
        int r = g >> 4, q = g & 15;
        unsigned dsw = (unsigned)(r * 256 + ((q ^ (r & 7)) << 4));
        LDGSTS16(db + dsw, sh + (size_t)g * 16);
    }
}
__device__ __forceinline__ void load_A(char* smem, int it, int t) {
    const uint4* sh = g_h + (size_t)it * 2048;
    #pragma unroll
    for (int i = 0; i < 8; i++) {
        int g = i * 256 + t;
        int r = g >> 4, q = g & 15;
        unsigned dsw = (unsigned)(r * 256 + ((q ^ (r & 7)) << 4));
        *(uint4*)(smem + SM_AH + dsw) = sh[g];
    }
}

// warp-0-only pair flush
__device__ __forceinline__ void flush_pairs_w0(unsigned* s_cnt, uint2* pbuf, int lane) {
    unsigned cnt = *s_cnt;
    if (cnt > PBUF_CAP) cnt = PBUF_CAP;
    unsigned gb = 0;
    if (lane == 0 && cnt) gb = atomicAdd(&g_np, cnt);
    gb = __shfl_sync(0xffffffffu, gb, 0);
    for (unsigned i = lane; i < cnt; i += 32) g_pairs[gb + i] = pbuf[i];
    if (lane == 0) *s_cnt = 0u;
}

__device__ __forceinline__ void advance(int& it, int& jt) {
    jt++; if (jt == NT) { it++; jt = it; }
}

// ---------------- persistent HMMA Gram + packed fused epilogue ----------------
__global__ void __launch_bounds__(256, 2) k_S() {
    extern __shared__ char smem[];
    const unsigned sb = smem_u32(smem);
    float* s_sqi  = (float*)(smem + SM_SQI);
    int*   s_li   = (int*)  (smem + SM_LI);
    unsigned* s_cnt = (unsigned*)(smem + SM_CNT);

    const int t = threadIdx.x, w = t >> 5, lane = t & 31;

    // balanced contiguous static split
    const int nb_ = gridDim.x;
    const int basec = NTILES / nb_, rem = NTILES % nb_;
    const int start = blockIdx.x * basec + min(blockIdx.x, rem);
    const int end = start + basec + (blockIdx.x < rem ? 1 : 0);
    if (start >= end) return;

    int cit = 0, base = 0;
    while (start >= base + (NT - cit)) { base += NT - cit; cit++; }
    int cjt = cit + (start - base);
    int nit = cit, njt = cjt; advance(nit, njt);     // tile k+1
    int pit = nit, pjt = njt; advance(pit, pjt);     // tile k+2

    // ---- preloop staging ----
    load_A(smem, cit, t);
    if (t < 128) {
        s_sqi[t] = g_sq[cit * TILE + t];
        s_li[t]  = g_lab[cit * TILE + t];
        *(float*)(smem + SM_SQJ(start & 1) + t * 4) = g_sq[cjt * TILE + t];
        *(int*)  (smem + SM_LJ(start & 1)  + t * 4) = g_lab[cjt * TILE + t];
    }
    issue_B(sb, start & 1, cjt, t); CP_COMMIT();
    if (start + 1 < end) { issue_B(sb, (start + 1) & 1, njt, t); CP_COMMIT(); }
    if (t == 0) { s_cnt[0] = 0u; s_cnt[1] = 0u; }
    __syncthreads();

    // warp subtile: 32 rows x 64 cols
    const int mb = (w & 3) * 32;
    const int nb = (w >> 2) * 64;
    const int a_row = mb + (lane & 15);
    const int a_ch  = lane >> 4;
    const int b_row = nb + (lane & 7) + ((lane >> 4) << 3);
    const int b_ch  = (lane >> 3) & 1;

    // packed constants; arg = (1-d)*log2e + 12 = fma(d, -log2e, log2e+12)
    // max arg (d=0) = 13.443 -> ex2 peak ~11127, ALWAYS finite in fp16.
    unsigned long long kNeg2, kNL2E, kCC;
    PACK2(kNeg2, -2.0f, -2.0f);
    PACK2(kNL2E, -1.44269504f, -1.44269504f);
    PACK2(kCC, 13.44269504f, 13.44269504f);

    for (int k = start; k < end; k++) {
        const int buf = k & 1;
        const bool offdiag = (cit != cjt);
        float* s_sqj = (float*)(smem + SM_SQJ(buf));
        int*   s_lj  = (int*)  (smem + SM_LJ(buf));
        uint2* pbuf  = (uint2*)(smem + SM_PBUF(buf));

        if (k + 1 < end) CP_WAIT1(); else CP_WAIT0();

        // ---- MMA ----
        float acc[2][8][4];
        #pragma unroll
        for (int mt = 0; mt < 2; mt++)
            #pragma unroll
            for (int nt = 0; nt < 8; nt++)
                #pragma unroll
                for (int e = 0; e < 4; e++) acc[mt][nt][e] = 0.0f;

        const unsigned bbase = sb + SM_B(buf);
        #pragma unroll
        for (int ks = 0; ks < 8; ks++) {
            unsigned ah[2][4], bh[8][2];
            #pragma unroll
            for (int mt = 0; mt < 2; mt++) {
                int r = a_row + mt * 16;
                unsigned addr = sb + SM_AH + r * 256 + (((ks * 2 + a_ch) ^ (r & 7)) << 4);
                LDSM4(ah[mt], addr);
            }
            #pragma unroll
            for (int np = 0; np < 4; np++) {
                int r = b_row + np * 16;
                unsigned addr = bbase + r * 256 + (((ks * 2 + b_ch) ^ (r & 7)) << 4);
                unsigned th[4];
                LDSM4(th, addr);
                bh[2*np][0] = th[0]; bh[2*np][1] = th[1];
                bh[2*np+1][0] = th[2]; bh[2*np+1][1] = th[3];
            }
            #pragma unroll
            for (int mt = 0; mt < 2; mt++)
                #pragma unroll
                for (int nt = 0; nt < 8; nt++)
                    MMA(acc[mt][nt], ah[mt], bh[nt]);
        }

        // stage sqj/lab for tile k+1 into opposite parity
        if (k + 1 < end && t < 128) {
            *(float*)(smem + SM_SQJ(1 - buf) + t * 4) = g_sq[njt * TILE + t];
            *(int*)  (smem + SM_LJ(1 - buf)  + t * 4) = g_lab[njt * TILE + t];
        }

        // ---- packed epilogue ----
        const int r4 = lane >> 2, cb = (lane & 3) * 2;
        float sqi_r[4]; int li_r[4];
        #pragma unroll
        for (int mt = 0; mt < 2; mt++)
            #pragma unroll
            for (int h = 0; h < 2; h++) {
                int iL = mb + mt * 16 + r4 + h * 8;
                sqi_r[mt*2+h] = s_sqi[iL]; li_r[mt*2+h] = s_li[iL];
            }
        // preload packed sqj / labels for this thread's 8 col-pairs
        unsigned long long sqj2[8]; int lj0a[8], lj1a[8];
        #pragma unroll
        for (int nt = 0; nt < 8; nt++) {
            float2 sv = *(const float2*)(s_sqj + nb + nt * 8 + cb);
            PACK2(sqj2[nt], sv.x, sv.y);
            int2 lv = *(const int2*)(s_lj + nb + nt * 8 + cb);
            lj0a[nt] = lv.x; lj1a[nt] = lv.y;
        }

        unsigned rp2[4] = {0u, 0u, 0u, 0u};
        unsigned cp2[8] = {0u, 0u, 0u, 0u, 0u, 0u, 0u, 0u};

        #pragma unroll
        for (int mt = 0; mt < 2; mt++)
            #pragma unroll
            for (int h = 0; h < 2; h++) {
                const int q = mt * 2 + h;
                const float ssq = sqi_r[q];
                const int li_ = li_r[q];
                unsigned long long sqi2;
                PACK2(sqi2, ssq, ssq);
                #pragma unroll
                for (int nt = 0; nt < 8; nt++) {
                    unsigned long long ssum, accp, d2p, dp, ap;
                    ADDX2(ssum, sqj2[nt], sqi2);
                    PACK2(accp, acc[mt][nt][h*2], acc[mt][nt][h*2+1]);
                    FMAX2(d2p, accp, kNeg2, ssum);
                    float d20, d21; UNPK2(d20, d21, d2p);
                    d20 = fmaxf(d20, EPSV); d21 = fmaxf(d21, EPSV);
                    float d0, d1;
                    asm("sqrt.approx.f32 %0, %1;" : "=f"(d0) : "f"(d20));
                    asm("sqrt.approx.f32 %0, %1;" : "=f"(d1) : "f"(d21));
                    PACK2(dp, d0, d1);
                    FMAX2(ap, dp, kNL2E, kCC);
                    float a0, a1; UNPK2(a0, a1, ap);
                    unsigned argh, ev;
                    CVTH2(argh, a1, a0);          // hi=a1, lo=a0
                    EX2H2(ev, argh);              // finite for all lanes (arg <= 13.45)
                    if (li_ == lj0a[nt] || li_ == lj1a[nt]) {   // rare
                        unsigned gi = cit * TILE + mb + mt * 16 + r4 + h * 8;
                        unsigned gj0 = cjt * TILE + nb + nt * 8 + cb;
                        if (li_ == lj0a[nt]) {
                            unsigned kk = atomicAdd(&s_cnt[buf], 1u);
                            unsigned packed = gi | (gj0 << 13) | (offdiag ? (1u << 26) : 0u);
                            uint2 rec = make_uint2(packed, __float_as_uint(d0));
                            if (kk < PBUF_CAP) pbuf[kk] = rec;
                            else { unsigned gg = atomicAdd(&g_np, 1u); if (gg < PAIR_CAP) g_pairs[gg] = rec; }
                            ev &= 0xFFFF0000u;
                        }
                        if (li_ == lj1a[nt]) {
                            unsigned kk = atomicAdd(&s_cnt[buf], 1u);
                            unsigned packed = gi | ((gj0 + 1) << 13) | (offdiag ? (1u << 26) : 0u);
                            uint2 rec = make_uint2(packed, __float_as_uint(d1));
                            if (kk < PBUF_CAP) pbuf[kk] = rec;
                            else { unsigned gg = atomicAdd(&g_np, 1u); if (gg < PAIR_CAP) g_pairs[gg] = rec; }
                            ev &= 0x0000FFFFu;
                        }
                    }
                    HADD2V(rp2[q], rp2[q], ev);
                    HADD2V(cp2[nt], cp2[nt], ev);
                }
            }

        // row sums: reduce over lane&3 axis, then lo+hi, -> global RED
        #pragma unroll
        for (int q = 0; q < 4; q++) {
            unsigned v = rp2[q], o;
            o = __shfl_xor_sync(0xffffffffu, v, 1); HADD2V(v, v, o);
            o = __shfl_xor_sync(0xffffffffu, v, 2); HADD2V(v, v, o);
            if ((lane & 3) == 0) {
                float flo, fhi; H2TOF(flo, fhi, v);
                atomicAdd(&g_S[cit * TILE + mb + (q >> 1) * 16 + r4 + (q & 1) * 8],
                          (flo + fhi) * SSCALE);
            }
        }
        // col sums: reduce over lane>>2 axis -> global RED (two cols per half2)
        if (offdiag) {
            #pragma unroll
            for (int nt = 0; nt < 8; nt++) {
                unsigned v = cp2[nt], o;
                o = __shfl_xor_sync(0xffffffffu, v, 4);  HADD2V(v, v, o);
                o = __shfl_xor_sync(0xffffffffu, v, 8);  HADD2V(v, v, o);
                o = __shfl_xor_sync(0xffffffffu, v, 16); HADD2V(v, v, o);
                if ((lane >> 2) == 0) {
                    float flo, fhi; H2TOF(flo, fhi, v);
                    int col = cjt * TILE + nb + nt * 8 + cb;
                    atomicAdd(&g_S[col], flo * SSCALE);
                    atomicAdd(&g_S[col + 1], fhi * SSCALE);
                }
            }
        }

        __syncthreads();     // SINGLE end-of-tile barrier

        // B(buf) free: prefetch tile k+2
        if (k + 2 < end) { issue_B(sb, buf, pjt, t); CP_COMMIT(); }

        // warp 0 drains this tile's pair buffer while others proceed
        if (w == 0) flush_pairs_w0(&s_cnt[buf], pbuf, lane);

        // A-band change: reload + extra barrier (rare)
        if (k + 1 < end && nit != cit) {
            load_A(smem, nit, t);
            if (t < 128) {
                s_sqi[t] = g_sq[nit * TILE + t];
                s_li[t]  = g_lab[nit * TILE + t];
            }
            __syncthreads();
        }

        cit = nit; cjt = njt;
        nit = pit; njt = pjt;
        advance(pit, pjt);
    }
}

// ---------------- positive-pair loss + fused finalize ----------------
__global__ void __launch_bounds__(256) k_pairs(float* out) {
    __shared__ float rf[256];
    __shared__ int   ri[256];
    unsigned n = g_np; if (n > PAIR_CAP) n = PAIR_CAP;
    float part = 0.0f; int c = 0;
    for (unsigned idx = blockIdx.x * 256u + threadIdx.x; idx < n; idx += gridDim.x * 256u) {
        uint2 p = g_pairs[idx];
        int i = p.x & 0x1FFF, j = (p.x >> 13) & 0x1FFF;
        int wt = (p.x & (1u << 26)) ? 2 : 1;
        float d = __uint_as_float(p.y);
        float J = __logf(g_S[i] + g_S[j]) + d;
        float h = fmaxf(J, 0.0f);
        part += (float)wt * h * h; c += wt;
    }
    int t = threadIdx.x;
    rf[t] = part; ri[t] = c;
    __syncthreads();
    for (int off = 128; off; off >>= 1) {
        if (t < off) { rf[t] += rf[t + off]; ri[t] += ri[t + off]; }
        __syncthreads();
    }
    if (t == 0) {
        atomicAdd(&g_loss, (double)rf[0]);
        atomicAdd(&g_cnt, (unsigned long long)ri[0]);
        __threadfence();
        unsigned v = atomicAdd(&g_done, 1u);
        if (v == gridDim.x - 1)
            out[0] = (float)(g_loss / (2.0 * (double)g_cnt));
    }
}

// ---------------- launcher ----------------
extern "C" void kernel_launch(void* const* d_in, const int* in_sizes, int n_in,
                              void* d_out, int out_size) {
    const float* f     = (const float*)d_in[0];
    const int*   lab32 = (const int*)d_in[1];
    float*       out   = (float*)d_out;

    int dev = 0, nsm = 0;
    if (cudaGetDevice(&dev) != cudaSuccess ||
        cudaDeviceGetAttribute(&nsm, cudaDevAttrMultiProcessorCount, dev) != cudaSuccess ||
        nsm <= 0)
        nsm = 148;

    cudaFuncSetAttribute(k_S, cudaFuncAttributeMaxDynamicSharedMemorySize, SM_TOTAL);

    k_prep<<<512, 256>>>(f, lab32);
    k_S<<<nsm * 2, 256, SM_TOTAL>>>();
    k_pairs<<<512, 256>>>(out);
}